// round 14
// baseline (speedup 1.0000x reference)
#include <cuda_runtime.h>

#define GN    6
#define NN    36
#define NB7   7            // 7x7 counter grid incl. trash row/col
#define NPED  8192
#define HID   128
#define RPB   128          // rows per block
#define NSL   16           // j-slices
#define JCH   (NPED / NSL) // 512
#define HB4   (NPED / 4)   // u32 words per (slice,bin)
#define HB16  (HB4 / 4)    // 512 uint4 per (slice,bin): 16 rows per uint4
#define NXB   (NPED / RPB) // 64 i-blocks

// Per-slice byte-packed partial counts (word w holds rows 4w..4w+3).
// Fully overwritten every launch -> no zeroing, replay-safe.
__device__ uint4 g8v[NSL * NN * HB16];   // 4.7 MB

// Arrival tickets, one per i-block. Zero-init; the 16th arriver (the reducer)
// resets its ticket to 0 -> invariant holds across graph replays.
__device__ unsigned g_ticket[NXB];

// ---------------------------------------------------------------------------
// Fused kernel: per-slice histogram (hot loop byte-identical to R8/R13,
// measured ~34-35us) + last-arriver reduction & embedding.
// ---------------------------------------------------------------------------
__global__ __launch_bounds__(RPB) void fused_kernel(const float* __restrict__ obs2,
                                                    const float* __restrict__ W,
                                                    const float* __restrict__ b,
                                                    float* __restrict__ out) {
    __shared__ unsigned   cnt[NB7 * NB7 * RPB];  // 25KB; reused as cs[36][128] by reducer
    __shared__ ulonglong2 pts[JCH / 2];          // 4 KB
    __shared__ unsigned   s_flag;

    const int t  = threadIdx.x;
    const int bx = blockIdx.x;
    const int i  = bx * RPB + t;
    const int j0 = blockIdx.y * JCH;

    // ---- Phase 1: histogram over this block's j-slice ----
    {
        const ulonglong2* src = (const ulonglong2*)(obs2 + 2 * j0);
#pragma unroll
        for (int k = 0; k < JCH / 2 / RPB; k++)
            pts[t + k * RPB] = src[t + k * RPB];
    }
#pragma unroll
    for (int k = 0; k < NB7 * NB7; k++)
        cnt[k * RPB + t] = 0u;

    const float2 pi = ((const float2*)obs2)[i];
    float nx = -pi.x, ny = -pi.y;
    unsigned long long negpi;
    asm("mov.b64 %0, {%1,%2};" : "=l"(negpi) : "f"(nx), "f"(ny));
    const unsigned long long THREE2 = 0x4040000040400000ULL;  // (3.0f, 3.0f)
    const float MAGIC = 8388608.0f;                           // 2^23

    __syncthreads();

    unsigned* mycnt = cnt + t;

#pragma unroll 4
    for (int k = 0; k < JCH / 2; k++) {
        const ulonglong2 pp = pts[k];   // LDS.128 broadcast: two points
#pragma unroll
        for (int half = 0; half < 2; half++) {
            const unsigned long long pj = half ? pp.y : pp.x;
            unsigned long long d, e;
            // EXACT reference order per lane: rn(pj - pi), then rn(+3)
            asm("add.rn.f32x2 %0, %1, %2;" : "=l"(d) : "l"(pj), "l"(negpi));
            asm("add.rn.f32x2 %0, %1, %2;" : "=l"(e) : "l"(d), "l"(THREE2));
            const float ex = __uint_as_float((unsigned)e);
            const float ey = __uint_as_float((unsigned)(e >> 32));
            float fx, fy;
            asm("add.rm.f32 %0, %1, %2;" : "=f"(fx) : "f"(ex), "f"(MAGIC));
            asm("add.rm.f32 %0, %1, %2;" : "=f"(fy) : "f"(ey), "f"(MAGIC));
            unsigned bx2 = __float_as_uint(fx) - 0x4B000000u;  // floor; OOR -> huge
            unsigned by2 = __float_as_uint(fy) - 0x4B000000u;
            bx2 = umin(bx2, 6u);
            by2 = umin(by2, 6u);
            mycnt[(bx2 * NB7 + by2) * RPB] += 1u;  // conflict-free RMW, no branch
        }
    }

    __syncthreads();  // flush reads other threads' counter columns

    // ---- Flush 36 valid bins, byte-packed 4 rows/word ----
    {
        const int sl = blockIdx.y;
        unsigned* g8 = (unsigned*)g8v;
#pragma unroll
        for (int k = 0; k < 9; k++) {
            const int gidx = k * RPB + t;     // 0..1151
            const int vb   = gidx >> 5;
            const int w    = gidx & 31;
            const int b49  = (vb / GN) * NB7 + (vb % GN);
            const unsigned b0 = cnt[b49 * RPB + 4 * w + 0];
            const unsigned b1 = cnt[b49 * RPB + 4 * w + 1];
            const unsigned b2 = cnt[b49 * RPB + 4 * w + 2];
            const unsigned b3 = cnt[b49 * RPB + 4 * w + 3];
            g8[(sl * NN + vb) * HB4 + bx * (RPB / 4) + w] =
                b0 | (b1 << 8) | (b2 << 16) | (b3 << 24);
        }
    }

    // ---- Ticket: last arriver for this i-block becomes the reducer ----
    __threadfence();                      // make g8 stores visible first
    if (t == 0) {
        const unsigned old = atomicAdd(&g_ticket[bx], 1u);
        s_flag = (old == NSL - 1) ? 1u : 0u;
    }
    __syncthreads();
    if (!s_flag) return;

    if (t == 0) g_ticket[bx] = 0u;        // restore for next graph replay

    // ---- Reducer: w row for h = t (L1-resident W), overlaps reduction ----
    float w[NN];
    {
        const float4* Wv = (const float4*)(W + t * NN);  // 144B offset: 16B aligned
#pragma unroll
        for (int q = 0; q < NN / 4; q++) {
            const float4 v = Wv[q];
            w[4 * q + 0] = v.x; w[4 * q + 1] = v.y;
            w[4 * q + 2] = v.z; w[4 * q + 3] = v.w;
        }
    }
    const float bh = b[t];

    // ---- Reduce 16 slices into cs[c][128] (reusing cnt smem) ----
    float* cs = (float*)cnt;              // cs[c * RPB + r], 4608 words <= 6272
    for (int task = t; task < NN * 8; task += RPB) {
        const int c     = task >> 3;
        const int chunk = task & 7;       // rows chunk*16 .. +15
        const uint4* gp = g8v + c * HB16 + bx * 8 + chunk;
        unsigned a[8];
#pragma unroll
        for (int q = 0; q < 8; q++) a[q] = 0u;
#pragma unroll
        for (int sl = 0; sl < NSL; sl++) {
            const uint4 v = gp[sl * NN * HB16];
            a[0] += __byte_perm(v.x, 0, 0x4140);
            a[1] += __byte_perm(v.x, 0, 0x4342);
            a[2] += __byte_perm(v.y, 0, 0x4140);
            a[3] += __byte_perm(v.y, 0, 0x4342);
            a[4] += __byte_perm(v.z, 0, 0x4140);
            a[5] += __byte_perm(v.z, 0, 0x4342);
            a[6] += __byte_perm(v.w, 0, 0x4140);
            a[7] += __byte_perm(v.w, 0, 0x4342);
        }
        const unsigned self = (c == 3 * GN + 3) ? 1u : 0u;   // self pair -> bin 21
        float* dst = cs + c * RPB + chunk * 16;
#pragma unroll
        for (int q = 0; q < 8; q++) {
            dst[2 * q + 0] = (float)((a[q] & 0xFFFFu) - self);
            dst[2 * q + 1] = (float)((a[q] >> 16)     - self);
        }
    }
    __syncthreads();

    // ---- Embedding GEMM: 128 rows x (h = t); cs reads are broadcasts ----
    float* orow = out + bx * RPB * HID + t;
#pragma unroll 8
    for (int r = 0; r < RPB; r++) {
        float acc = bh;
#pragma unroll
        for (int c = 0; c < NN; c++)
            acc = fmaf(cs[c * RPB + r], w[c], acc);
        orow[r * HID] = acc;              // coalesced STG.32
    }
}

// ---------------------------------------------------------------------------
// Inputs: 0 hidden_state (unused), 1 obs1 (unused), 2 obs2 [8192,2],
// 3 W [128,36], 4 b [128]. Output fp32 [8192,128].
// ---------------------------------------------------------------------------
extern "C" void kernel_launch(void* const* d_in, const int* in_sizes, int n_in,
                              void* d_out, int out_size) {
    const float* obs2 = (const float*)d_in[2];
    const float* W    = (const float*)d_in[3];
    const float* b    = (const float*)d_in[4];
    float*       out  = (float*)d_out;

    dim3 g1(NXB, NSL);                    // 64 x 16 = 1024 blocks, one launch
    fused_kernel<<<g1, RPB>>>(obs2, W, b, out);
}

// round 15
// speedup vs baseline: 1.1924x; 1.1924x over previous
#include <cuda_runtime.h>

#define GN    6
#define NN    36
#define NB7   7            // 7x7 counter grid incl. trash row/col
#define NPED  8192
#define HID   128
#define RPB   128          // rows per count block (proven 28 warps/SM config)
#define NSL   16           // j-slices
#define JCH   (NPED / NSL) // 512
#define HB4   (NPED / 4)   // 2048 u32 words per (slice,bin): 4 byte-packed rows/word

// Per-slice byte-packed partial counts (word w holds rows 4w..4w+3).
// Fully overwritten by count_kernel every launch -> no zeroing, replay-safe.
__device__ unsigned g8[NSL * NN * HB4];   // 4.7 MB

// W transposed: WT[c*HID + h] = W[h*NN + c]. Written cooperatively by the 16
// count blocks with blockIdx.x == 0 (disjoint idx ranges); read by embed.
__device__ float g_WT[NN * HID];

// ---------------------------------------------------------------------------
// Phase 1: branch-free occupancy histogram, conflict-free u32 counters.
// Byte-identical to R12 (measured 35.1us: issue-slot floor + spread transpose).
// ---------------------------------------------------------------------------
__global__ __launch_bounds__(RPB) void count_kernel(const float* __restrict__ obs2,
                                                    const float* __restrict__ W) {
    __shared__ unsigned   cnt[NB7 * NB7 * RPB];  // [bin49][t], bank = t%32 (conflict-free)
    __shared__ ulonglong2 pts[JCH / 2];          // 4 KB

    const int t  = threadIdx.x;
    const int i  = blockIdx.x * RPB + t;
    const int j0 = blockIdx.y * JCH;

    // Cooperative W transpose: block (0,sl) handles idx [sl*288, (sl+1)*288).
    if (blockIdx.x == 0) {
        const int base = blockIdx.y * (HID * NN / NSL);
        for (int idx = base + t; idx < base + HID * NN / NSL; idx += RPB) {
            const int h = idx / NN;
            const int c = idx - h * NN;
            g_WT[c * HID + h] = W[idx];
        }
    }

    {
        const ulonglong2* src = (const ulonglong2*)(obs2 + 2 * j0);
#pragma unroll
        for (int k = 0; k < JCH / 2 / RPB; k++)
            pts[t + k * RPB] = src[t + k * RPB];
    }
#pragma unroll
    for (int k = 0; k < NB7 * NB7; k++)
        cnt[k * RPB + t] = 0u;

    const float2 pi = ((const float2*)obs2)[i];
    float nx = -pi.x, ny = -pi.y;
    unsigned long long negpi;
    asm("mov.b64 %0, {%1,%2};" : "=l"(negpi) : "f"(nx), "f"(ny));
    const unsigned long long THREE2 = 0x4040000040400000ULL;  // (3.0f, 3.0f)
    const float MAGIC = 8388608.0f;                           // 2^23

    __syncthreads();

    unsigned* mycnt = cnt + t;

#pragma unroll 4
    for (int k = 0; k < JCH / 2; k++) {
        const ulonglong2 pp = pts[k];   // LDS.128 broadcast: two points
#pragma unroll
        for (int half = 0; half < 2; half++) {
            const unsigned long long pj = half ? pp.y : pp.x;
            unsigned long long d, e;
            // EXACT reference order per lane: rn(pj - pi), then rn(+3)
            asm("add.rn.f32x2 %0, %1, %2;" : "=l"(d) : "l"(pj), "l"(negpi));
            asm("add.rn.f32x2 %0, %1, %2;" : "=l"(e) : "l"(d), "l"(THREE2));
            const float ex = __uint_as_float((unsigned)e);
            const float ey = __uint_as_float((unsigned)(e >> 32));
            float fx, fy;
            asm("add.rm.f32 %0, %1, %2;" : "=f"(fx) : "f"(ex), "f"(MAGIC));
            asm("add.rm.f32 %0, %1, %2;" : "=f"(fy) : "f"(ey), "f"(MAGIC));
            unsigned bx = __float_as_uint(fx) - 0x4B000000u;  // floor; OOR -> huge
            unsigned by = __float_as_uint(fy) - 0x4B000000u;
            bx = umin(bx, 6u);
            by = umin(by, 6u);
            mycnt[(bx * NB7 + by) * RPB] += 1u;  // conflict-free RMW, no branch
        }
    }

    __syncthreads();

    // Flush 36 valid bins, byte-packed 4 rows/word (per-slice counts < 255).
    const int sl = blockIdx.y;
#pragma unroll
    for (int k = 0; k < 9; k++) {
        const int gidx = k * RPB + t;     // 0..1151
        const int vb   = gidx >> 5;
        const int w    = gidx & 31;
        const int b49  = (vb / GN) * NB7 + (vb % GN);
        const unsigned b0 = cnt[b49 * RPB + 4 * w + 0];
        const unsigned b1 = cnt[b49 * RPB + 4 * w + 1];
        const unsigned b2 = cnt[b49 * RPB + 4 * w + 2];
        const unsigned b3 = cnt[b49 * RPB + 4 * w + 3];
        g8[(sl * NN + vb) * HB4 + blockIdx.x * (RPB / 4) + w] =
            b0 | (b1 << 8) | (b2 << 16) | (b3 << 24);
    }
}

// ---------------------------------------------------------------------------
// Phase 2: 1024 blocks x 128 thr, 8 rows/block, one h per thread.
// cs stored TRANSPOSED [c][8] so one LDS.128 broadcast = 4 rows; 8
// independent accumulators -> FMA chain latency fully hidden (dep dist 8).
// ---------------------------------------------------------------------------
__global__ __launch_bounds__(HID) void embed_kernel(const float* __restrict__ b,
                                                    float* __restrict__ out) {
    __shared__ float cs[NN * 8];   // cs[c*8 + r], r = row 0..7

    const int t  = threadIdx.x;    // == h
    const int i0 = blockIdx.x * 8;

    // w loads first: lane-consecutive in h -> coalesced; WT L1/L2-resident.
    // Latency overlaps phase A.
    float w[NN];
#pragma unroll
    for (int c = 0; c < NN; c++)
        w[c] = g_WT[c * HID + t];
    const float bh = b[t];

    // Phase A: one bin per lane (t<36); 16 aligned uint2 loads (8 rows each),
    // packed-u16 accumulation (max 960 < 65536). Self pair -> bin 21.
    if (t < NN) {
        unsigned a[4] = {0u, 0u, 0u, 0u};
        const uint2* gv = (const uint2*)g8;
#pragma unroll
        for (int sl = 0; sl < NSL; sl++) {
            const uint2 v = gv[(sl * NN + t) * (HB4 / 2) + blockIdx.x];
            a[0] += __byte_perm(v.x, 0, 0x4140);  // rows 0,1
            a[1] += __byte_perm(v.x, 0, 0x4342);  // rows 2,3
            a[2] += __byte_perm(v.y, 0, 0x4140);  // rows 4,5
            a[3] += __byte_perm(v.y, 0, 0x4342);  // rows 6,7
        }
        const unsigned self = (t == 3 * GN + 3) ? 1u : 0u;
#pragma unroll
        for (int q = 0; q < 4; q++) {
            cs[t * 8 + 2 * q + 0] = (float)((a[q] & 0xFFFFu) - self);
            cs[t * 8 + 2 * q + 1] = (float)((a[q] >> 16)     - self);
        }
    }
    __syncthreads();

    // Phase B: 8 independent accumulators; per c: 2x LDS.128 broadcast + 8 FMA.
    float acc[8];
#pragma unroll
    for (int r = 0; r < 8; r++) acc[r] = bh;

#pragma unroll
    for (int c = 0; c < NN; c++) {
        const float4 v0 = *(const float4*)&cs[c * 8 + 0];  // rows 0..3
        const float4 v1 = *(const float4*)&cs[c * 8 + 4];  // rows 4..7
        const float wc = w[c];
        acc[0] = fmaf(v0.x, wc, acc[0]);
        acc[1] = fmaf(v0.y, wc, acc[1]);
        acc[2] = fmaf(v0.z, wc, acc[2]);
        acc[3] = fmaf(v0.w, wc, acc[3]);
        acc[4] = fmaf(v1.x, wc, acc[4]);
        acc[5] = fmaf(v1.y, wc, acc[5]);
        acc[6] = fmaf(v1.z, wc, acc[6]);
        acc[7] = fmaf(v1.w, wc, acc[7]);
    }

#pragma unroll
    for (int r = 0; r < 8; r++)
        out[(i0 + r) * HID + t] = acc[r];   // coalesced STG.32
}

// ---------------------------------------------------------------------------
// Inputs: 0 hidden_state (unused), 1 obs1 (unused), 2 obs2 [8192,2],
// 3 W [128,36], 4 b [128]. Output fp32 [8192,128].
// ---------------------------------------------------------------------------
extern "C" void kernel_launch(void* const* d_in, const int* in_sizes, int n_in,
                              void* d_out, int out_size) {
    const float* obs2 = (const float*)d_in[2];
    const float* W    = (const float*)d_in[3];
    const float* b    = (const float*)d_in[4];
    float*       out  = (float*)d_out;

    dim3 g1(NPED / RPB, NSL);        // 64 x 16 = 1024 blocks
    count_kernel<<<g1, RPB>>>(obs2, W);
    embed_kernel<<<NPED / 8, HID>>>(b, out);
}

// round 16
// speedup vs baseline: 1.1932x; 1.0007x over previous
#include <cuda_runtime.h>

#define GN    6
#define NN    36
#define NB7   7            // 7x7 counter grid incl. trash row/col
#define NPED  8192
#define HID   128
#define RPB   128          // rows per count block (proven 28 warps/SM config)
#define NSL   16           // j-slices
#define JCH   (NPED / NSL) // 512
#define NXB8  (NPED / 8)   // 1024 groups of 8 rows
#define GW    72           // words per (bx8, sl): 36 bins x 2 words (4 rows each)

// Byte-packed partial counts, EMBED-MAJOR layout:
//   g8[(bx8*NSL + sl)*GW + c*2 + w2], bytes = rows bx8*8 + w2*4 + {0,1,2,3}.
// Each embed block reads one contiguous 4.6KB chunk (fully coalesced).
// Fully overwritten by count_kernel every launch -> no zeroing, replay-safe.
__device__ unsigned g8[NXB8 * NSL * GW];   // 4.7 MB

// W transposed: WT[c*HID + h] = W[h*NN + c]. Written cooperatively by the 16
// count blocks with blockIdx.x == 0 (disjoint idx ranges); read by embed.
__device__ float g_WT[NN * HID];

// ---------------------------------------------------------------------------
// Phase 1: branch-free occupancy histogram, conflict-free u32 counters.
// Hot loop byte-identical to R12/R15 (measured ~34-35us, issue-slot floor).
// ---------------------------------------------------------------------------
__global__ __launch_bounds__(RPB) void count_kernel(const float* __restrict__ obs2,
                                                    const float* __restrict__ W) {
    __shared__ unsigned   cnt[NB7 * NB7 * RPB];  // [bin49][t], bank = t%32 (conflict-free)
    __shared__ ulonglong2 pts[JCH / 2];          // 4 KB

    const int t  = threadIdx.x;
    const int i  = blockIdx.x * RPB + t;
    const int j0 = blockIdx.y * JCH;

    // Cooperative W transpose: block (0,sl) handles idx [sl*288, (sl+1)*288).
    if (blockIdx.x == 0) {
        const int base = blockIdx.y * (HID * NN / NSL);
        for (int idx = base + t; idx < base + HID * NN / NSL; idx += RPB) {
            const int h = idx / NN;
            const int c = idx - h * NN;
            g_WT[c * HID + h] = W[idx];
        }
    }

    {
        const ulonglong2* src = (const ulonglong2*)(obs2 + 2 * j0);
#pragma unroll
        for (int k = 0; k < JCH / 2 / RPB; k++)
            pts[t + k * RPB] = src[t + k * RPB];
    }
#pragma unroll
    for (int k = 0; k < NB7 * NB7; k++)
        cnt[k * RPB + t] = 0u;

    const float2 pi = ((const float2*)obs2)[i];
    float nx = -pi.x, ny = -pi.y;
    unsigned long long negpi;
    asm("mov.b64 %0, {%1,%2};" : "=l"(negpi) : "f"(nx), "f"(ny));
    const unsigned long long THREE2 = 0x4040000040400000ULL;  // (3.0f, 3.0f)
    const float MAGIC = 8388608.0f;                           // 2^23

    __syncthreads();

    unsigned* mycnt = cnt + t;

#pragma unroll 4
    for (int k = 0; k < JCH / 2; k++) {
        const ulonglong2 pp = pts[k];   // LDS.128 broadcast: two points
#pragma unroll
        for (int half = 0; half < 2; half++) {
            const unsigned long long pj = half ? pp.y : pp.x;
            unsigned long long d, e;
            // EXACT reference order per lane: rn(pj - pi), then rn(+3)
            asm("add.rn.f32x2 %0, %1, %2;" : "=l"(d) : "l"(pj), "l"(negpi));
            asm("add.rn.f32x2 %0, %1, %2;" : "=l"(e) : "l"(d), "l"(THREE2));
            const float ex = __uint_as_float((unsigned)e);
            const float ey = __uint_as_float((unsigned)(e >> 32));
            float fx, fy;
            asm("add.rm.f32 %0, %1, %2;" : "=f"(fx) : "f"(ex), "f"(MAGIC));
            asm("add.rm.f32 %0, %1, %2;" : "=f"(fy) : "f"(ey), "f"(MAGIC));
            unsigned bx = __float_as_uint(fx) - 0x4B000000u;  // floor; OOR -> huge
            unsigned by = __float_as_uint(fy) - 0x4B000000u;
            bx = umin(bx, 6u);
            by = umin(by, 6u);
            mycnt[(bx * NB7 + by) * RPB] += 1u;  // conflict-free RMW, no branch
        }
    }

    __syncthreads();  // flush reads other threads' counter columns

    // Flush into embed-major layout. Thread t, iter k:
    //   g    = t>>3      (8-row group 0..15 within this i-block)
    //   slot = (t&7)+k*8 (0..71: c = slot>>1, w2 = slot&1)
    // Warp = 4 g-groups x 8 consecutive words -> 4x32B runs (same cost as
    // a fully coalesced STG.32 warp: 4 sectors).
    const int sl = blockIdx.y;
    {
        const int g    = t >> 3;
        const int lane8 = t & 7;
        unsigned* dst = &g8[((blockIdx.x * 16 + g) * NSL + sl) * GW];
        const unsigned* csrc = cnt + g * 8;   // rows g*8 .. g*8+7 live here + b49*RPB
#pragma unroll
        for (int k = 0; k < 9; k++) {
            const int slot = lane8 + k * 8;   // 0..71
            const int c    = slot >> 1;
            const int w2   = slot & 1;
            const int b49  = (c / GN) * NB7 + (c % GN);
            const unsigned* p = csrc + b49 * RPB + w2 * 4;
            dst[slot] = p[0] | (p[1] << 8) | (p[2] << 16) | (p[3] << 24);
        }
    }
}

// ---------------------------------------------------------------------------
// Phase 2: 1024 blocks x 128 thr, 8 rows/block. The block's entire partial
// data is one contiguous 4.6KB chunk: 9 coalesced LDG.32 per thread -> smem,
// 72 lanes reduce over slices, then R15's 8-accumulator GEMM.
// ---------------------------------------------------------------------------
__global__ __launch_bounds__(HID) void embed_kernel(const float* __restrict__ b,
                                                    float* __restrict__ out) {
    __shared__ unsigned raw[NSL * GW];   // 4.6KB staged chunk: raw[sl*72 + slot]
    __shared__ float    cs[NN * 8];      // cs[c*8 + r]

    const int t  = threadIdx.x;          // == h
    const int i0 = blockIdx.x * 8;

    // Stage the chunk: fully coalesced, MLP 9.
    {
        const unsigned* src = &g8[blockIdx.x * (NSL * GW)];
#pragma unroll
        for (int k = 0; k < 9; k++)
            raw[k * HID + t] = src[k * HID + t];
    }

    // w loads (overlap with staging latency): coalesced, WT L1/L2-resident.
    float w[NN];
#pragma unroll
    for (int c = 0; c < NN; c++)
        w[c] = g_WT[c * HID + t];
    const float bh = b[t];

    __syncthreads();

    // Reduce over slices: 72 lanes, task t = (c = t>>1, w2 = t&1).
    // raw stride 72: within a warp banks are distinct (t%32 all different).
    if (t < GW) {
        unsigned a01 = 0u, a23 = 0u;
#pragma unroll
        for (int sl = 0; sl < NSL; sl++) {
            const unsigned v = raw[sl * GW + t];
            a01 += __byte_perm(v, 0, 0x4140);   // rows +0,+1 as u16 pair
            a23 += __byte_perm(v, 0, 0x4342);   // rows +2,+3
        }
        const int c  = t >> 1;
        const int w2 = t & 1;
        const unsigned self = (c == 3 * GN + 3) ? 1u : 0u;   // self pair -> bin 21
        float* dst = &cs[c * 8 + w2 * 4];
        dst[0] = (float)((a01 & 0xFFFFu) - self);
        dst[1] = (float)((a01 >> 16)     - self);
        dst[2] = (float)((a23 & 0xFFFFu) - self);
        dst[3] = (float)((a23 >> 16)     - self);
    }
    __syncthreads();

    // Phase B: 8 independent accumulators; per c: 2x LDS.128 broadcast + 8 FMA.
    float acc[8];
#pragma unroll
    for (int r = 0; r < 8; r++) acc[r] = bh;

#pragma unroll
    for (int c = 0; c < NN; c++) {
        const float4 v0 = *(const float4*)&cs[c * 8 + 0];  // rows 0..3
        const float4 v1 = *(const float4*)&cs[c * 8 + 4];  // rows 4..7
        const float wc = w[c];
        acc[0] = fmaf(v0.x, wc, acc[0]);
        acc[1] = fmaf(v0.y, wc, acc[1]);
        acc[2] = fmaf(v0.z, wc, acc[2]);
        acc[3] = fmaf(v0.w, wc, acc[3]);
        acc[4] = fmaf(v1.x, wc, acc[4]);
        acc[5] = fmaf(v1.y, wc, acc[5]);
        acc[6] = fmaf(v1.z, wc, acc[6]);
        acc[7] = fmaf(v1.w, wc, acc[7]);
    }

#pragma unroll
    for (int r = 0; r < 8; r++)
        out[(i0 + r) * HID + t] = acc[r];   // coalesced STG.32
}

// ---------------------------------------------------------------------------
// Inputs: 0 hidden_state (unused), 1 obs1 (unused), 2 obs2 [8192,2],
// 3 W [128,36], 4 b [128]. Output fp32 [8192,128].
// ---------------------------------------------------------------------------
extern "C" void kernel_launch(void* const* d_in, const int* in_sizes, int n_in,
                              void* d_out, int out_size) {
    const float* obs2 = (const float*)d_in[2];
    const float* W    = (const float*)d_in[3];
    const float* b    = (const float*)d_in[4];
    float*       out  = (float*)d_out;

    dim3 g1(NPED / RPB, NSL);        // 64 x 16 = 1024 blocks
    count_kernel<<<g1, RPB>>>(obs2, W);
    embed_kernel<<<NXB8, HID>>>(b, out);
}

// round 17
// speedup vs baseline: 1.2271x; 1.0284x over previous
#include <cuda_runtime.h>

#define GN    6
#define NN    36
#define NB7   7            // 7x7 counter grid incl. trash row/col
#define NPED  8192
#define HID   128
#define RPB   128          // rows per count block (proven 28 warps/SM config)
#define NSL   16           // j-slices
#define JCH   (NPED / NSL) // 512
#define NXB8  (NPED / 8)   // 1024 groups of 8 rows
#define GW    72           // words per (bx8, sl): slot = bw*8 + r8, word = bins 4bw..4bw+3 of row r8

// Byte-packed partial counts, EMBED-MAJOR layout:
//   g8[(bx8*NSL + sl)*GW + bw*8 + r8], byte j = count(row bx8*8+r8, bin 4bw+j).
// Each embed block reads one contiguous 4.6KB chunk (fully coalesced).
// Fully overwritten by count_kernel every launch -> no zeroing, replay-safe.
__device__ unsigned g8[NXB8 * NSL * GW];   // 4.7 MB

// W transposed: WT[c*HID + h] = W[h*NN + c]. Written cooperatively by the 16
// count blocks with blockIdx.x == 0 (disjoint idx ranges); read by embed.
__device__ float g_WT[NN * HID];

// ---------------------------------------------------------------------------
// Phase 1: branch-free occupancy histogram, conflict-free u32 counters.
// Hot loop byte-identical to R12/R15 (measured ~33-35us, issue-slot floor).
// Flush: each thread reads ITS OWN counter column (bank = t%32, zero
// conflicts, immediate offsets) and packs 4 bins/word with byte_perm.
// ---------------------------------------------------------------------------
__global__ __launch_bounds__(RPB) void count_kernel(const float* __restrict__ obs2,
                                                    const float* __restrict__ W) {
    __shared__ unsigned   cnt[NB7 * NB7 * RPB];  // [bin49][t], bank = t%32 (conflict-free)
    __shared__ ulonglong2 pts[JCH / 2];          // 4 KB

    const int t  = threadIdx.x;
    const int i  = blockIdx.x * RPB + t;
    const int j0 = blockIdx.y * JCH;

    // Cooperative W transpose: block (0,sl) handles idx [sl*288, (sl+1)*288).
    if (blockIdx.x == 0) {
        const int base = blockIdx.y * (HID * NN / NSL);
        for (int idx = base + t; idx < base + HID * NN / NSL; idx += RPB) {
            const int h = idx / NN;
            const int c = idx - h * NN;
            g_WT[c * HID + h] = W[idx];
        }
    }

    {
        const ulonglong2* src = (const ulonglong2*)(obs2 + 2 * j0);
#pragma unroll
        for (int k = 0; k < JCH / 2 / RPB; k++)
            pts[t + k * RPB] = src[t + k * RPB];
    }
#pragma unroll
    for (int k = 0; k < NB7 * NB7; k++)
        cnt[k * RPB + t] = 0u;

    const float2 pi = ((const float2*)obs2)[i];
    float nx = -pi.x, ny = -pi.y;
    unsigned long long negpi;
    asm("mov.b64 %0, {%1,%2};" : "=l"(negpi) : "f"(nx), "f"(ny));
    const unsigned long long THREE2 = 0x4040000040400000ULL;  // (3.0f, 3.0f)
    const float MAGIC = 8388608.0f;                           // 2^23

    __syncthreads();

    unsigned* mycnt = cnt + t;

#pragma unroll 4
    for (int k = 0; k < JCH / 2; k++) {
        const ulonglong2 pp = pts[k];   // LDS.128 broadcast: two points
#pragma unroll
        for (int half = 0; half < 2; half++) {
            const unsigned long long pj = half ? pp.y : pp.x;
            unsigned long long d, e;
            // EXACT reference order per lane: rn(pj - pi), then rn(+3)
            asm("add.rn.f32x2 %0, %1, %2;" : "=l"(d) : "l"(pj), "l"(negpi));
            asm("add.rn.f32x2 %0, %1, %2;" : "=l"(e) : "l"(d), "l"(THREE2));
            const float ex = __uint_as_float((unsigned)e);
            const float ey = __uint_as_float((unsigned)(e >> 32));
            float fx, fy;
            asm("add.rm.f32 %0, %1, %2;" : "=f"(fx) : "f"(ex), "f"(MAGIC));
            asm("add.rm.f32 %0, %1, %2;" : "=f"(fy) : "f"(ey), "f"(MAGIC));
            unsigned bx = __float_as_uint(fx) - 0x4B000000u;  // floor; OOR -> huge
            unsigned by = __float_as_uint(fy) - 0x4B000000u;
            bx = umin(bx, 6u);
            by = umin(by, 6u);
            mycnt[(bx * NB7 + by) * RPB] += 1u;  // conflict-free RMW, no branch
        }
    }

    __syncthreads();  // (keeps warps in lockstep before the store burst)

    // Flush: thread t = row i. Read own column (36 conflict-free LDS with
    // compile-time offsets), pack bins 4bw..4bw+3 per word, store 9 words.
    // Warp stores per bw: 4 runs of 8 consecutive words = 4 sectors.
    {
        const int g  = t >> 3;        // 8-row group within this i-block
        const int r8 = t & 7;         // row within group
        unsigned* dst = &g8[((blockIdx.x * 16 + g) * NSL + blockIdx.y) * GW + r8];
#pragma unroll
        for (int bw = 0; bw < 9; bw++) {
            // bins c = 4bw+j ; b49(c) = (c/6)*7 + c%6 -- all compile-time
            const int c0 = 4 * bw;
            const unsigned p0 = mycnt[(((c0 + 0) / GN) * NB7 + (c0 + 0) % GN) * RPB];
            const unsigned p1 = mycnt[(((c0 + 1) / GN) * NB7 + (c0 + 1) % GN) * RPB];
            const unsigned p2 = mycnt[(((c0 + 2) / GN) * NB7 + (c0 + 2) % GN) * RPB];
            const unsigned p3 = mycnt[(((c0 + 3) / GN) * NB7 + (c0 + 3) % GN) * RPB];
            const unsigned lo = __byte_perm(p0, p1, 0x0040);  // (p0b0, p1b0)
            const unsigned hi = __byte_perm(p2, p3, 0x0040);  // (p2b0, p3b0)
            dst[bw * 8] = __byte_perm(lo, hi, 0x5410);        // 4 bins packed
        }
    }
}

// ---------------------------------------------------------------------------
// Phase 2: 1024 blocks x 128 thr, 8 rows/block. Block data = one contiguous
// 4.6KB chunk: coalesced stage -> 72-lane slice reduction (word = 4 bins of
// one row) -> 8-accumulator GEMM (unchanged from R16: measured 7.9us).
// ---------------------------------------------------------------------------
__global__ __launch_bounds__(HID) void embed_kernel(const float* __restrict__ b,
                                                    float* __restrict__ out) {
    __shared__ unsigned raw[NSL * GW];   // 4.6KB: raw[sl*72 + bw*8 + r8]
    __shared__ float    cs[NN * 8];      // cs[c*8 + r]

    const int t  = threadIdx.x;          // == h
    const int i0 = blockIdx.x * 8;

    // Stage the chunk: fully coalesced, MLP 9.
    {
        const unsigned* src = &g8[blockIdx.x * (NSL * GW)];
#pragma unroll
        for (int k = 0; k < 9; k++)
            raw[k * HID + t] = src[k * HID + t];
    }

    // w loads (overlap with staging latency): coalesced, WT L1/L2-resident.
    float w[NN];
#pragma unroll
    for (int c = 0; c < NN; c++)
        w[c] = g_WT[c * HID + t];
    const float bh = b[t];

    __syncthreads();

    // Reduce over slices: 72 lanes; task t = (bw = t>>3, r8 = t&7).
    // Word = bins 4bw..4bw+3 of row r8; packed-u16 sums (max 960 < 65536).
    if (t < GW) {
        unsigned a01 = 0u, a23 = 0u;
#pragma unroll
        for (int sl = 0; sl < NSL; sl++) {
            const unsigned v = raw[sl * GW + t];   // banks distinct per warp
            a01 += __byte_perm(v, 0, 0x4140);      // bins 4bw+0, 4bw+1
            a23 += __byte_perm(v, 0, 0x4342);      // bins 4bw+2, 4bw+3
        }
        const int bw = t >> 3;
        const int r8 = t & 7;
        const int c0 = 4 * bw;
        // Self pair (always bin 21 = 4*5+1): subtract where c == 21.
        cs[(c0 + 0) * 8 + r8] = (float)((a01 & 0xFFFFu) - ((c0 + 0 == 21) ? 1u : 0u));
        cs[(c0 + 1) * 8 + r8] = (float)((a01 >> 16)     - ((c0 + 1 == 21) ? 1u : 0u));
        cs[(c0 + 2) * 8 + r8] = (float)((a23 & 0xFFFFu) - ((c0 + 2 == 21) ? 1u : 0u));
        cs[(c0 + 3) * 8 + r8] = (float)((a23 >> 16)     - ((c0 + 3 == 21) ? 1u : 0u));
    }
    __syncthreads();

    // Phase B: 8 independent accumulators; per c: 2x LDS.128 broadcast + 8 FMA.
    float acc[8];
#pragma unroll
    for (int r = 0; r < 8; r++) acc[r] = bh;

#pragma unroll
    for (int c = 0; c < NN; c++) {
        const float4 v0 = *(const float4*)&cs[c * 8 + 0];  // rows 0..3
        const float4 v1 = *(const float4*)&cs[c * 8 + 4];  // rows 4..7
        const float wc = w[c];
        acc[0] = fmaf(v0.x, wc, acc[0]);
        acc[1] = fmaf(v0.y, wc, acc[1]);
        acc[2] = fmaf(v0.z, wc, acc[2]);
        acc[3] = fmaf(v0.w, wc, acc[3]);
        acc[4] = fmaf(v1.x, wc, acc[4]);
        acc[5] = fmaf(v1.y, wc, acc[5]);
        acc[6] = fmaf(v1.z, wc, acc[6]);
        acc[7] = fmaf(v1.w, wc, acc[7]);
    }

#pragma unroll
    for (int r = 0; r < 8; r++)
        out[(i0 + r) * HID + t] = acc[r];   // coalesced STG.32
}

// ---------------------------------------------------------------------------
// Inputs: 0 hidden_state (unused), 1 obs1 (unused), 2 obs2 [8192,2],
// 3 W [128,36], 4 b [128]. Output fp32 [8192,128].
// ---------------------------------------------------------------------------
extern "C" void kernel_launch(void* const* d_in, const int* in_sizes, int n_in,
                              void* d_out, int out_size) {
    const float* obs2 = (const float*)d_in[2];
    const float* W    = (const float*)d_in[3];
    const float* b    = (const float*)d_in[4];
    float*       out  = (float*)d_out;

    dim3 g1(NPED / RPB, NSL);        // 64 x 16 = 1024 blocks
    count_kernel<<<g1, RPB>>>(obs2, W);
    embed_kernel<<<NXB8, HID>>>(b, out);
}